// round 4
// baseline (speedup 1.0000x reference)
#include <cuda_runtime.h>
#include <cstdint>

#define N_INST 64
#define HW 64000   // 200*320
#define MASK_ELEMS (N_INST * HW)

// Scratch (no cudaMalloc allowed): column-major O, g_Ocol[j*64 + i] = O[i][j]
__device__ float g_Ocol[N_INST * N_INST];

__device__ __forceinline__ float sigmoidf_(float x) {
    return __fdividef(1.0f, 1.0f + __expf(-x));
}

__device__ __forceinline__ unsigned long long pack2_(float lo, float hi) {
    unsigned long long d;
    asm("mov.b64 %0, {%1, %2};" : "=l"(d) : "f"(lo), "f"(hi));
    return d;
}

__device__ __forceinline__ void unpack2_(unsigned long long v, float& lo, float& hi) {
    asm("mov.b64 {%0, %1}, %2;" : "=f"(lo), "=f"(hi) : "l"(v));
}

// Packed 2xfp32 FMA (SASS FFMA2) — only reachable via PTX fma.rn.f32x2
__device__ __forceinline__ unsigned long long fma2_(unsigned long long a,
                                                    unsigned long long b,
                                                    unsigned long long c) {
    unsigned long long d;
    asm("fma.rn.f32x2 %0, %1, %2, %3;" : "=l"(d) : "l"(a), "l"(b), "l"(c));
    return d;
}

// ---------------------------------------------------------------------------
// Kernel 1: one warp per unordered pair (i<j). Both logits computed once;
// exactly one of O[i,j]/O[j,i] is nonzero, both written. Separate warps
// zero the diagonal. Writes row-major out_O and column-major g_Ocol.
// ---------------------------------------------------------------------------
__global__ void relation_O_kernel(const float* __restrict__ bbox,
                                  const int*   __restrict__ cls_idx,
                                  const float* __restrict__ U_w,   // (256,80)
                                  const float* __restrict__ V_w,   // (256,80)
                                  const float* __restrict__ Wc_w,  // (128,4)
                                  const float* __restrict__ P_w,   // (384,)
                                  float* __restrict__ out_O)
{
    int warp = (blockIdx.x * blockDim.x + threadIdx.x) >> 5;
    int lane = threadIdx.x & 31;
    const int NPAIR = (N_INST * (N_INST - 1)) / 2;   // 2016
    if (warp >= NPAIR + N_INST) return;

    if (warp >= NPAIR) {                              // diagonal zeros
        if (lane == 0) {
            int i = warp - NPAIR;
            out_O[i * 64 + i]  = 0.f;
            g_Ocol[i * 64 + i] = 0.f;
        }
        return;
    }

    // decode i < j from triangular index: warp = j*(j-1)/2 + i
    int j = (int)((1.0f + sqrtf(8.0f * (float)warp + 1.0f)) * 0.5f);
    while (j * (j - 1) / 2 > warp) j--;
    while ((j + 1) * j / 2 <= warp) j++;
    int i = warp - j * (j - 1) / 2;

    int ki = cls_idx[i] - 1;
    int kj = cls_idx[j] - 1;

    float s_ij = 0.f, s_ji = 0.f;

    #pragma unroll
    for (int c = lane; c < 256; c += 32) {
        float ui = fmaxf(U_w[c * 80 + ki], 0.f);
        float uj = fmaxf(U_w[c * 80 + kj], 0.f);
        float vi = fmaxf(V_w[c * 80 + ki], 0.f);
        float vj = fmaxf(V_w[c * 80 + kj], 0.f);
        float p  = P_w[c];
        s_ij += ui * vj * p;
        s_ji += uj * vi * p;
    }

    float x0i = bbox[i * 5 + 1], y0i = bbox[i * 5 + 2];
    float x1i = bbox[i * 5 + 3], y1i = bbox[i * 5 + 4];
    float x0j = bbox[j * 5 + 1], y0j = bbox[j * 5 + 2];
    float x1j = bbox[j * 5 + 3], y1j = bbox[j * 5 + 4];
    float wi = x1i - x0i + 1.f, hi = y1i - y0i + 1.f;
    float wj = x1j - x0j + 1.f, hj = y1j - y0j + 1.f;
    float xci = x0i + 0.5f * wi, yci = y0i + 0.5f * hi;
    float xcj = x0j + 0.5f * wj, ycj = y0j + 0.5f * hj;

    float dx_ij = -(xci - xcj) / wi, dy_ij = -(yci - ycj) / hi;
    float dw_ij = __logf(wj / wi),   dh_ij = __logf(hj / hi);
    float dx_ji = -(xcj - xci) / wj, dy_ji = -(ycj - yci) / hj;
    float dw_ji = __logf(wi / wj),   dh_ji = __logf(hi / hj);

    #pragma unroll
    for (int o = lane; o < 128; o += 32) {
        float4 w4 = *reinterpret_cast<const float4*>(&Wc_w[o * 4]);
        float p = P_w[256 + o];
        float a = dx_ij * w4.x + dy_ij * w4.y + dw_ij * w4.z + dh_ij * w4.w;
        float b = dx_ji * w4.x + dy_ji * w4.y + dw_ji * w4.z + dh_ji * w4.w;
        s_ij += fmaxf(a, 0.f) * p;
        s_ji += fmaxf(b, 0.f) * p;
    }

    #pragma unroll
    for (int off = 16; off; off >>= 1) {
        s_ij += __shfl_xor_sync(0xffffffffu, s_ij, off);
        s_ji += __shfl_xor_sync(0xffffffffu, s_ji, off);
    }

    if (lane == 0) {
        float r_ij = sigmoidf_(s_ij);
        float r_ji = sigmoidf_(s_ji);
        float o_ij = fmaxf(r_ij - r_ji, 0.f);
        float o_ji = fmaxf(r_ji - r_ij, 0.f);
        out_O[i * 64 + j]  = o_ij;
        out_O[j * 64 + i]  = o_ji;
        g_Ocol[j * 64 + i] = o_ij;   // column j, row i
        g_Ocol[i * 64 + j] = o_ji;
    }
}

// ---------------------------------------------------------------------------
// Kernel 2: mask update. blockIdx.y selects which 32-row i-half this block
// owns. Each thread owns 2 adjacent pixels. Accumulators are paired along i
// (acc pair g = (w[2g], w[2g+1]) for one pixel) so the FFMA2 multiplier is
// two consecutive O-column floats read straight from smem (8 LDS.128/j,
// no duplication table); the splat moves to t (2 packs/j). 2-deep LDG
// prefetch on the mask row.
// ---------------------------------------------------------------------------
__global__ void __launch_bounds__(256, 2)
mask_update_kernel(const float* __restrict__ mask, float* __restrict__ out)
{
    __shared__ __align__(16) float Osh[64 * 32];  // [j][i_local], plain floats

    int tid = threadIdx.x;
    int ibase = blockIdx.y * 32;

    // coalesced copy of this i-half's O columns
    #pragma unroll
    for (int k = tid; k < 2048; k += 256) {
        int j = k >> 5, il = k & 31;
        Osh[j * 32 + il] = g_Ocol[j * 64 + (ibase + il)];
    }
    __syncthreads();

    int p = (blockIdx.x * 256 + tid) * 2;

    // acc pair g: (w[ibase+2g], w[ibase+2g+1]); separate sets for pixel 0/1
    unsigned long long acc0[16], acc1[16];
    #pragma unroll
    for (int g = 0; g < 16; g++) { acc0[g] = 0ull; acc1[g] = 0ull; }

    float2 mmA = *reinterpret_cast<const float2*>(mask + p);                   // j
    float2 mmB = *reinterpret_cast<const float2*>(mask + (size_t)HW + p);      // j+1

    #pragma unroll 1
    for (int j = 0; j < 64; j++) {
        float2 mm = mmA;
        mmA = mmB;
        if (j < 62)
            mmB = *reinterpret_cast<const float2*>(mask + (size_t)(j + 2) * HW + p);
        float t0 = sigmoidf_(mm.x);
        float t1 = sigmoidf_(mm.y);
        unsigned long long td0 = pack2_(t0, t0);
        unsigned long long td1 = pack2_(t1, t1);
        const ulonglong2* ocol = reinterpret_cast<const ulonglong2*>(&Osh[j * 32]);
        #pragma unroll
        for (int g = 0; g < 8; g++) {
            ulonglong2 o2 = ocol[g];   // floats {4g..4g+3} as two (lo,hi) pairs
            acc0[2 * g + 0] = fma2_(o2.x, td0, acc0[2 * g + 0]);
            acc1[2 * g + 0] = fma2_(o2.x, td1, acc1[2 * g + 0]);
            acc0[2 * g + 1] = fma2_(o2.y, td0, acc0[2 * g + 1]);
            acc1[2 * g + 1] = fma2_(o2.y, td1, acc1[2 * g + 1]);
        }
    }

    #pragma unroll
    for (int g = 0; g < 16; g++) {
        int i0 = ibase + 2 * g;
        int i1 = i0 + 1;
        float w0_p0, w1_p0, w0_p1, w1_p1;
        unpack2_(acc0[g], w0_p0, w1_p0);   // pixel p:   w[i0], w[i1]
        unpack2_(acc1[g], w0_p1, w1_p1);   // pixel p+1: w[i0], w[i1]

        float2 m0 = *reinterpret_cast<const float2*>(mask + (size_t)i0 * HW + p);
        float2 m1 = *reinterpret_cast<const float2*>(mask + (size_t)i1 * HW + p);

        float2 r0, r1;
        r0.x = m0.x - m0.x * sigmoidf_(m0.x) * w0_p0;
        r0.y = m0.y - m0.y * sigmoidf_(m0.y) * w0_p1;
        r1.x = m1.x - m1.x * sigmoidf_(m1.x) * w1_p0;
        r1.y = m1.y - m1.y * sigmoidf_(m1.y) * w1_p1;

        *reinterpret_cast<float2*>(out + (size_t)i0 * HW + p) = r0;
        *reinterpret_cast<float2*>(out + (size_t)i1 * HW + p) = r1;
    }
}

extern "C" void kernel_launch(void* const* d_in, const int* in_sizes, int n_in,
                              void* d_out, int out_size)
{
    const float* mask    = (const float*)d_in[0];
    const float* bbox    = (const float*)d_in[1];
    const int*   cls_idx = (const int*)  d_in[2];
    const float* U_w     = (const float*)d_in[3];
    const float* V_w     = (const float*)d_in[4];
    const float* Wc_w    = (const float*)d_in[5];
    const float* P_w     = (const float*)d_in[6];

    float* out_mask = (float*)d_out;                 // 4,096,000 elems
    float* out_O    = (float*)d_out + MASK_ELEMS;    // 4,096 elems

    // 2016 pair-warps + 64 diagonal warps = 2080 warps -> 260 blocks x 256
    relation_O_kernel<<<260, 256>>>(bbox, cls_idx, U_w, V_w, Wc_w, P_w, out_O);

    // 125 pixel chunks x 2 i-halves
    dim3 grid(125, 2);
    mask_update_kernel<<<grid, 256>>>(mask, out_mask);
}